// round 8
// baseline (speedup 1.0000x reference)
#include <cuda_runtime.h>
#include <math.h>
#include <stdint.h>

// R8: classic SGEMM register tiling with f32x2. CTA = 128 pts x 128 ch,
// 256 threads, thread tile 8x8 (32 f32x2 accs). Basis in smem (not regs!),
// per K-step 6 LDS.128 -> 32 FFMA2. Coefficients pre-duplicated (c,c) u64.

#define NPTS    110592
#define NB      30
#define NOI     256
#define THREADS 256

struct WParams { float w[NB]; };

__device__ __forceinline__ void basis_eval(float r, float th, float ph,
                                           float* __restrict__ bas)
{
    const float ct  = cosf(th);
    const float st2 = fmaxf(1.0f - ct * ct, 0.0f);
    const float st  = sqrtf(st2);
    const float cp  = cosf(ph);
    const float sp  = sinf(ph);
    const float c2p = cp * cp - sp * sp;
    const float s2p = 2.0f * sp * cp;
    const float c3p = c2p * cp - s2p * sp;
    const float s3p = s2p * cp + c2p * sp;

    const float er1 = expf(-r);
    const float er2 = expf(-0.5f * r);
    const float er3 = expf(-0.33333333333333333f * r);
    const float er4 = expf(-0.25f * r);
    const float rho3 = 0.66666666666666666f * r;
    const float rho4 = 0.5f * r;

    const float F10 = er1;
    const float F20 = er2 * (2.0f - r);
    const float F21 = er2 * r;
    const float F30 = er3 * (3.0f + rho3 * (-3.0f + 0.5f * rho3));
    const float F31 = er3 * rho3 * (4.0f - rho3);
    const float F32 = er3 * rho3 * rho3;
    const float F40 = er4 * (4.0f + rho4 * (-6.0f + rho4 * (2.0f - 0.16666666666666666f * rho4)));
    const float F41 = er4 * rho4 * (10.0f + rho4 * (-5.0f + 0.5f * rho4));
    const float F42 = er4 * rho4 * rho4 * (6.0f - rho4);
    const float F43 = er4 * rho4 * rho4 * rho4;

    const float p10 = ct;
    const float p11 = -st;
    const float p20 = 1.5f * ct * ct - 0.5f;
    const float p21 = -3.0f * ct * st;
    const float p22 = 3.0f * st2;
    const float p30 = (2.5f * ct * ct - 1.5f) * ct;
    const float p31 = (1.5f - 7.5f * ct * ct) * st;
    const float p32 = 15.0f * ct * st2;
    const float p33 = -15.0f * st * st2;

    bas[0]  = F10;
    bas[1]  = F20;
    bas[2]  = F21 * p11 * sp;
    bas[3]  = F21 * p10;
    bas[4]  = F21 * p11 * cp;
    bas[5]  = F30;
    bas[6]  = F31 * p11 * sp;
    bas[7]  = F31 * p10;
    bas[8]  = F31 * p11 * cp;
    bas[9]  = F32 * p22 * s2p;
    bas[10] = F32 * p21 * sp;
    bas[11] = F32 * p20;
    bas[12] = F32 * p21 * cp;
    bas[13] = F32 * p22 * c2p;
    bas[14] = F40;
    bas[15] = F41 * p11 * sp;
    bas[16] = F41 * p10;
    bas[17] = F41 * p11 * cp;
    bas[18] = F42 * p22 * s2p;
    bas[19] = F42 * p21 * sp;
    bas[20] = F42 * p20;
    bas[21] = F42 * p21 * cp;
    bas[22] = F42 * p22 * c2p;
    bas[23] = F43 * p33 * s3p;
    bas[24] = F43 * p32 * s2p;
    bas[25] = F43 * p31 * sp;
    bas[26] = F43 * p30;
    bas[27] = F43 * p31 * cp;
    bas[28] = F43 * p32 * c2p;
    bas[29] = F43 * p33 * c3p;
}

__global__ __launch_bounds__(THREADS, 2)
void dcconv_tile_gemm(const float* __restrict__ pos,
                      const float* __restrict__ coef,
                      float* __restrict__ out,
                      WParams W)
{
    __shared__ float              Asm[NB * 128];   // [k][pt]  15360 B
    __shared__ unsigned long long Bsm[NB * 128];   // [k][ch] dup (c,c)  30720 B

    const int tid   = threadIdx.x;
    const int half  = blockIdx.x & 1;            // channel half
    const int ptile = blockIdx.x >> 1;           // point tile
    const int ptid  = tid & 15;                  // 16 point-thread cols (8 pts each)
    const int chid  = tid >> 4;                  // 16 channel-thread rows (8 ch each)

    // ---- stage B: coef * w, duplicated u64 ----
    for (int idx = tid; idx < NB * 128; idx += THREADS) {
        const int k  = idx >> 7;
        const int ch = idx & 127;
        const float v = coef[(half * 128 + ch) * NB + k] * W.w[k];
        unsigned long long d;
        asm("mov.b64 %0, {%1, %1};" : "=l"(d) : "f"(v));
        Bsm[k * 128 + ch] = d;
    }

    // ---- stage A: threads 0..127 compute one point's basis each ----
    if (tid < 128) {
        const int p = ptile * 128 + tid;
        float bas[NB];
        basis_eval(pos[3 * p + 0], pos[3 * p + 1], pos[3 * p + 2], bas);
#pragma unroll
        for (int k = 0; k < NB; ++k)
            Asm[k * 128 + tid] = bas[k];
    }
    __syncthreads();

    // ---- mainloop: per k, 6 LDS.128 -> 32 FFMA2 ----
    unsigned long long acc[8][4];
#pragma unroll
    for (int c = 0; c < 8; ++c)
#pragma unroll
        for (int q = 0; q < 4; ++q)
            acc[c][q] = 0ULL;

#pragma unroll 3
    for (int k = 0; k < NB; ++k) {
        const ulonglong2* arow = (const ulonglong2*)(Asm + k * 128);
        const ulonglong2 a01 = arow[ptid * 2];       // pts 0-3 (2 pairs)
        const ulonglong2 a23 = arow[ptid * 2 + 1];   // pts 4-7
        const ulonglong2* brow = (const ulonglong2*)(Bsm + k * 128);
        const ulonglong2 b01 = brow[chid * 4];
        const ulonglong2 b23 = brow[chid * 4 + 1];
        const ulonglong2 b45 = brow[chid * 4 + 2];
        const ulonglong2 b67 = brow[chid * 4 + 3];
        const unsigned long long bv[8] = { b01.x, b01.y, b23.x, b23.y,
                                           b45.x, b45.y, b67.x, b67.y };
        const unsigned long long av[4] = { a01.x, a01.y, a23.x, a23.y };
#pragma unroll
        for (int c = 0; c < 8; ++c)
#pragma unroll
            for (int q = 0; q < 4; ++q)
                asm("fma.rn.f32x2 %0, %1, %2, %0;"
                    : "+l"(acc[c][q]) : "l"(av[q]), "l"(bv[c]));
    }

    // ---- epilogue: 8 channels x 8 consecutive points (2 STG.128 each) ----
    const int p0 = ptile * 128 + ptid * 8;
    const int c0 = half * 128 + chid * 8;
#pragma unroll
    for (int c = 0; c < 8; ++c) {
        float* o = out + (size_t)(c0 + c) * NPTS + p0;
        *(ulonglong2*)(o)     = make_ulonglong2(acc[c][0], acc[c][1]);
        *(ulonglong2*)(o + 4) = make_ulonglong2(acc[c][2], acc[c][3]);
    }
}

extern "C" void kernel_launch(void* const* d_in, const int* in_sizes, int n_in,
                              void* d_out, int out_size)
{
    const float* pos  = (const float*)d_in[0];
    const float* coef = (const float*)d_in[1];
    if (n_in >= 2 && in_sizes[0] == NOI * NB) {
        coef = (const float*)d_in[0];
        pos  = (const float*)d_in[1];
    }

    const double PI  = 3.14159265358979323846;
    const double K00 = sqrt(1.0 / (4.0 * PI));
    const double K10 = sqrt(3.0 / (4.0 * PI));
    const double K20 = sqrt(5.0 / (4.0 * PI));
    const double K30 = sqrt(7.0 / (4.0 * PI));
    const double A11 = sqrt(3.0 / (4.0 * PI));
    const double A21 = sqrt(5.0 / (12.0 * PI));
    const double A22 = sqrt(5.0 / (48.0 * PI));
    const double A31 = sqrt(7.0 / (24.0 * PI));
    const double A32 = sqrt(7.0 / (240.0 * PI));
    const double A33 = sqrt(7.0 / (1440.0 * PI));

    const double C10 = 2.0;
    const double C20 = sqrt(1.0 / 8.0);
    const double C21 = sqrt(1.0 / 24.0);
    const double C30 = sqrt(16.0 / 972.0);
    const double C31 = sqrt(8.0 / 3888.0);
    const double C32 = sqrt(8.0 / 19440.0);
    const double C40 = sqrt(6.0 / 1536.0);
    const double C41 = sqrt(2.0 / 7680.0);
    const double C42 = sqrt(1.0 / 46080.0);
    const double C43 = sqrt(1.0 / 322560.0);

    WParams W;
    const double w[NB] = {
        C10 * K00,
        C20 * K00,
        C21 * A11, C21 * K10, C21 * A11,
        C30 * K00,
        C31 * A11, C31 * K10, C31 * A11,
        C32 * A22, C32 * A21, C32 * K20, C32 * A21, C32 * A22,
        C40 * K00,
        C41 * A11, C41 * K10, C41 * A11,
        C42 * A22, C42 * A21, C42 * K20, C42 * A21, C42 * A22,
        C43 * A33, C43 * A32, C43 * A31, C43 * K30,
        C43 * A31, C43 * A32, C43 * A33
    };
    for (int i = 0; i < NB; ++i) W.w[i] = (float)w[i];

    // 2 blocks per point tile (channel halves) -> grid 1728
    dcconv_tile_gemm<<<2 * (NPTS / 128), THREADS>>>(pos, coef, (float*)d_out, W);
    (void)out_size;
}

// round 9
// speedup vs baseline: 1.6997x; 1.6997x over previous
#include <cuda_runtime.h>
#include <math.h>
#include <stdint.h>

// R9: R6 datapath, channel groups of 2 (I$-resident ~2.4KB inner body,
// fewer live accs -> lower regs -> +warps). Per b: 1 broadcast LDS.128
// -> 4 FFMA2 (ratio 4:1). 4 pts/thread register basis, channel-half split.

#define NPTS    110592
#define NB      30
#define NOI     256
#define NGH     64              // channel groups of 2 per half (128 ch/half)
#define THREADS 128

struct WParams { float w[NB]; };

__device__ __forceinline__ void basis_eval(float r, float th, float ph,
                                           const float* __restrict__ w,
                                           float* __restrict__ bas)
{
    const float ct  = cosf(th);
    const float st2 = fmaxf(1.0f - ct * ct, 0.0f);
    const float st  = sqrtf(st2);
    const float cp  = cosf(ph);
    const float sp  = sinf(ph);
    const float c2p = cp * cp - sp * sp;
    const float s2p = 2.0f * sp * cp;
    const float c3p = c2p * cp - s2p * sp;
    const float s3p = s2p * cp + c2p * sp;

    const float er1 = expf(-r);
    const float er2 = expf(-0.5f * r);
    const float er3 = expf(-0.33333333333333333f * r);
    const float er4 = expf(-0.25f * r);
    const float rho3 = 0.66666666666666666f * r;
    const float rho4 = 0.5f * r;

    const float F10 = er1;
    const float F20 = er2 * (2.0f - r);
    const float F21 = er2 * r;
    const float F30 = er3 * (3.0f + rho3 * (-3.0f + 0.5f * rho3));
    const float F31 = er3 * rho3 * (4.0f - rho3);
    const float F32 = er3 * rho3 * rho3;
    const float F40 = er4 * (4.0f + rho4 * (-6.0f + rho4 * (2.0f - 0.16666666666666666f * rho4)));
    const float F41 = er4 * rho4 * (10.0f + rho4 * (-5.0f + 0.5f * rho4));
    const float F42 = er4 * rho4 * rho4 * (6.0f - rho4);
    const float F43 = er4 * rho4 * rho4 * rho4;

    const float p10 = ct;
    const float p11 = -st;
    const float p20 = 1.5f * ct * ct - 0.5f;
    const float p21 = -3.0f * ct * st;
    const float p22 = 3.0f * st2;
    const float p30 = (2.5f * ct * ct - 1.5f) * ct;
    const float p31 = (1.5f - 7.5f * ct * ct) * st;
    const float p32 = 15.0f * ct * st2;
    const float p33 = -15.0f * st * st2;

    bas[0]  = w[0]  * F10;
    bas[1]  = w[1]  * F20;
    bas[2]  = w[2]  * F21 * p11 * sp;
    bas[3]  = w[3]  * F21 * p10;
    bas[4]  = w[4]  * F21 * p11 * cp;
    bas[5]  = w[5]  * F30;
    bas[6]  = w[6]  * F31 * p11 * sp;
    bas[7]  = w[7]  * F31 * p10;
    bas[8]  = w[8]  * F31 * p11 * cp;
    bas[9]  = w[9]  * F32 * p22 * s2p;
    bas[10] = w[10] * F32 * p21 * sp;
    bas[11] = w[11] * F32 * p20;
    bas[12] = w[12] * F32 * p21 * cp;
    bas[13] = w[13] * F32 * p22 * c2p;
    bas[14] = w[14] * F40;
    bas[15] = w[15] * F41 * p11 * sp;
    bas[16] = w[16] * F41 * p10;
    bas[17] = w[17] * F41 * p11 * cp;
    bas[18] = w[18] * F42 * p22 * s2p;
    bas[19] = w[19] * F42 * p21 * sp;
    bas[20] = w[20] * F42 * p20;
    bas[21] = w[21] * F42 * p21 * cp;
    bas[22] = w[22] * F42 * p22 * c2p;
    bas[23] = w[23] * F43 * p33 * s3p;
    bas[24] = w[24] * F43 * p32 * s2p;
    bas[25] = w[25] * F43 * p31 * sp;
    bas[26] = w[26] * F43 * p30;
    bas[27] = w[27] * F43 * p31 * cp;
    bas[28] = w[28] * F43 * p32 * c2p;
    bas[29] = w[29] * F43 * p33 * c3p;
}

__global__ __launch_bounds__(THREADS)
void dcconv_regbasis_g2(const float* __restrict__ pos,
                        const float* __restrict__ coef,
                        float* __restrict__ out,
                        WParams W)
{
    // scw2[g*60 + b*2 + i] = duplicated u64 (c,c), c = coef[(ch0+2g+i)*30+b]
    // 64 * 30 * 2 * 8 = 30720 bytes (static)
    __shared__ unsigned long long scw2[NGH * NB * 2];

    const int tid   = threadIdx.x;
    const int half  = blockIdx.x & 1;            // channel half: 0 or 1
    const int ptile = blockIdx.x >> 1;           // point tile
    const int ch0   = half * 128;
    const int p0    = (ptile * THREADS + tid) * 4;   // 4 adjacent points

    // ---- stage duplicated coefficients for this half's 128 channels ----
    for (int idx = tid; idx < NGH * NB * 2; idx += THREADS) {
        const int g   = idx / 60;
        const int rem = idx - g * 60;
        const int b   = rem >> 1;
        const int i   = rem & 1;
        const float c = coef[(ch0 + 2 * g + i) * NB + b];
        unsigned long long d;
        asm("mov.b64 %0, {%1, %1};" : "=l"(d) : "f"(c));
        scw2[idx] = d;
    }

    // ---- basis for the 4 points, norms folded in, packed as point-pairs ----
    const float4* pp = (const float4*)(pos + 3 * p0);   // 12 floats, 16B aligned
    const float4 q0 = pp[0];   // r0 th0 ph0 r1
    const float4 q1 = pp[1];   // th1 ph1 r2 th2
    const float4 q2 = pp[2];   // ph2 r3 th3 ph3

    float ba[NB], bb[NB], bc[NB], bd_[NB];
    basis_eval(q0.x, q0.y, q0.z, W.w, ba);
    basis_eval(q0.w, q1.x, q1.y, W.w, bb);
    basis_eval(q1.z, q1.w, q2.x, W.w, bc);
    basis_eval(q2.y, q2.z, q2.w, W.w, bd_);

    unsigned long long bd0[NB], bd1[NB];
#pragma unroll
    for (int b = 0; b < NB; ++b) {
        asm("mov.b64 %0, {%1, %2};" : "=l"(bd0[b]) : "f"(ba[b]), "f"(bb[b]));
        asm("mov.b64 %0, {%1, %2};" : "=l"(bd1[b]) : "f"(bc[b]), "f"(bd_[b]));
    }

    __syncthreads();

    // ---- channel-group loop (2 ch): per b, 1 broadcast LDS.128 -> 4 FFMA2 ----
    const unsigned long long* cg = scw2;
    float* ob = out + (size_t)ch0 * NPTS + p0;
#pragma unroll 1
    for (int g = 0; g < NGH; ++g) {
        unsigned long long a00 = 0ULL, a01 = 0ULL;   // ch+0 : pairs (p0p1),(p2p3)
        unsigned long long a10 = 0ULL, a11 = 0ULL;   // ch+1
#pragma unroll
        for (int b = 0; b < NB; ++b) {
            const ulonglong2 c01 = *(const ulonglong2*)(cg + b * 2);   // LDS.128 bcast
            asm("fma.rn.f32x2 %0, %1, %2, %0;" : "+l"(a00) : "l"(bd0[b]), "l"(c01.x));
            asm("fma.rn.f32x2 %0, %1, %2, %0;" : "+l"(a01) : "l"(bd1[b]), "l"(c01.x));
            asm("fma.rn.f32x2 %0, %1, %2, %0;" : "+l"(a10) : "l"(bd0[b]), "l"(c01.y));
            asm("fma.rn.f32x2 %0, %1, %2, %0;" : "+l"(a11) : "l"(bd1[b]), "l"(c01.y));
        }
        *(ulonglong2*)(ob)        = make_ulonglong2(a00, a01);   // STG.128, coalesced
        *(ulonglong2*)(ob + NPTS) = make_ulonglong2(a10, a11);
        cg += NB * 2;
        ob += 2 * NPTS;
    }
}

extern "C" void kernel_launch(void* const* d_in, const int* in_sizes, int n_in,
                              void* d_out, int out_size)
{
    const float* pos  = (const float*)d_in[0];
    const float* coef = (const float*)d_in[1];
    if (n_in >= 2 && in_sizes[0] == NOI * NB) {
        coef = (const float*)d_in[0];
        pos  = (const float*)d_in[1];
    }

    const double PI  = 3.14159265358979323846;
    const double K00 = sqrt(1.0 / (4.0 * PI));
    const double K10 = sqrt(3.0 / (4.0 * PI));
    const double K20 = sqrt(5.0 / (4.0 * PI));
    const double K30 = sqrt(7.0 / (4.0 * PI));
    const double A11 = sqrt(3.0 / (4.0 * PI));
    const double A21 = sqrt(5.0 / (12.0 * PI));
    const double A22 = sqrt(5.0 / (48.0 * PI));
    const double A31 = sqrt(7.0 / (24.0 * PI));
    const double A32 = sqrt(7.0 / (240.0 * PI));
    const double A33 = sqrt(7.0 / (1440.0 * PI));

    const double C10 = 2.0;
    const double C20 = sqrt(1.0 / 8.0);
    const double C21 = sqrt(1.0 / 24.0);
    const double C30 = sqrt(16.0 / 972.0);
    const double C31 = sqrt(8.0 / 3888.0);
    const double C32 = sqrt(8.0 / 19440.0);
    const double C40 = sqrt(6.0 / 1536.0);
    const double C41 = sqrt(2.0 / 7680.0);
    const double C42 = sqrt(1.0 / 46080.0);
    const double C43 = sqrt(1.0 / 322560.0);

    WParams W;
    const double w[NB] = {
        C10 * K00,
        C20 * K00,
        C21 * A11, C21 * K10, C21 * A11,
        C30 * K00,
        C31 * A11, C31 * K10, C31 * A11,
        C32 * A22, C32 * A21, C32 * K20, C32 * A21, C32 * A22,
        C40 * K00,
        C41 * A11, C41 * K10, C41 * A11,
        C42 * A22, C42 * A21, C42 * K20, C42 * A21, C42 * A22,
        C43 * A33, C43 * A32, C43 * A31, C43 * K30,
        C43 * A31, C43 * A32, C43 * A33
    };
    for (int i = 0; i < NB; ++i) W.w[i] = (float)w[i];

    // 2 blocks per point tile (channel halves) -> grid 432/... (NPTS/(4*128))*2 = 432
    dcconv_regbasis_g2<<<2 * (NPTS / (4 * THREADS)), THREADS>>>(pos, coef, (float*)d_out, W);
    (void)out_size;
}

// round 11
// speedup vs baseline: 1.7009x; 1.0007x over previous
#include <cuda_runtime.h>
#include <math.h>
#include <stdint.h>

// R11: R10 with the inline-asm typo fixed ("{%1, %2};" not "{%1, %2;}").
// g-loop unroll x2 (8 acc chains, cross-group LDS pipelining),
// __launch_bounds__(128,3) caps regs so occupancy cannot collapse.
// Per b: 2 broadcast LDS.128 -> 8 FFMA2. 4 pts/thread register basis.

#define NPTS    110592
#define NB      30
#define NOI     256
#define NGH     64              // channel groups of 2 per half (128 ch/half)
#define THREADS 128

struct WParams { float w[NB]; };

__device__ __forceinline__ void basis_eval(float r, float th, float ph,
                                           const float* __restrict__ w,
                                           float* __restrict__ bas)
{
    const float ct  = cosf(th);
    const float st2 = fmaxf(1.0f - ct * ct, 0.0f);
    const float st  = sqrtf(st2);
    const float cp  = cosf(ph);
    const float sp  = sinf(ph);
    const float c2p = cp * cp - sp * sp;
    const float s2p = 2.0f * sp * cp;
    const float c3p = c2p * cp - s2p * sp;
    const float s3p = s2p * cp + c2p * sp;

    const float er1 = expf(-r);
    const float er2 = expf(-0.5f * r);
    const float er3 = expf(-0.33333333333333333f * r);
    const float er4 = expf(-0.25f * r);
    const float rho3 = 0.66666666666666666f * r;
    const float rho4 = 0.5f * r;

    const float F10 = er1;
    const float F20 = er2 * (2.0f - r);
    const float F21 = er2 * r;
    const float F30 = er3 * (3.0f + rho3 * (-3.0f + 0.5f * rho3));
    const float F31 = er3 * rho3 * (4.0f - rho3);
    const float F32 = er3 * rho3 * rho3;
    const float F40 = er4 * (4.0f + rho4 * (-6.0f + rho4 * (2.0f - 0.16666666666666666f * rho4)));
    const float F41 = er4 * rho4 * (10.0f + rho4 * (-5.0f + 0.5f * rho4));
    const float F42 = er4 * rho4 * rho4 * (6.0f - rho4);
    const float F43 = er4 * rho4 * rho4 * rho4;

    const float p10 = ct;
    const float p11 = -st;
    const float p20 = 1.5f * ct * ct - 0.5f;
    const float p21 = -3.0f * ct * st;
    const float p22 = 3.0f * st2;
    const float p30 = (2.5f * ct * ct - 1.5f) * ct;
    const float p31 = (1.5f - 7.5f * ct * ct) * st;
    const float p32 = 15.0f * ct * st2;
    const float p33 = -15.0f * st * st2;

    bas[0]  = w[0]  * F10;
    bas[1]  = w[1]  * F20;
    bas[2]  = w[2]  * F21 * p11 * sp;
    bas[3]  = w[3]  * F21 * p10;
    bas[4]  = w[4]  * F21 * p11 * cp;
    bas[5]  = w[5]  * F30;
    bas[6]  = w[6]  * F31 * p11 * sp;
    bas[7]  = w[7]  * F31 * p10;
    bas[8]  = w[8]  * F31 * p11 * cp;
    bas[9]  = w[9]  * F32 * p22 * s2p;
    bas[10] = w[10] * F32 * p21 * sp;
    bas[11] = w[11] * F32 * p20;
    bas[12] = w[12] * F32 * p21 * cp;
    bas[13] = w[13] * F32 * p22 * c2p;
    bas[14] = w[14] * F40;
    bas[15] = w[15] * F41 * p11 * sp;
    bas[16] = w[16] * F41 * p10;
    bas[17] = w[17] * F41 * p11 * cp;
    bas[18] = w[18] * F42 * p22 * s2p;
    bas[19] = w[19] * F42 * p21 * sp;
    bas[20] = w[20] * F42 * p20;
    bas[21] = w[21] * F42 * p21 * cp;
    bas[22] = w[22] * F42 * p22 * c2p;
    bas[23] = w[23] * F43 * p33 * s3p;
    bas[24] = w[24] * F43 * p32 * s2p;
    bas[25] = w[25] * F43 * p31 * sp;
    bas[26] = w[26] * F43 * p30;
    bas[27] = w[27] * F43 * p31 * cp;
    bas[28] = w[28] * F43 * p32 * c2p;
    bas[29] = w[29] * F43 * p33 * c3p;
}

__global__ __launch_bounds__(THREADS, 3)
void dcconv_regbasis_u2(const float* __restrict__ pos,
                        const float* __restrict__ coef,
                        float* __restrict__ out,
                        WParams W)
{
    // scw2[g*60 + b*2 + i] = duplicated u64 (c,c), c = coef[(ch0+2g+i)*30+b]
    __shared__ unsigned long long scw2[NGH * NB * 2];   // 30720 B

    const int tid   = threadIdx.x;
    const int half  = blockIdx.x & 1;
    const int ptile = blockIdx.x >> 1;
    const int ch0   = half * 128;
    const int p0    = (ptile * THREADS + tid) * 4;

    for (int idx = tid; idx < NGH * NB * 2; idx += THREADS) {
        const int g   = idx / 60;
        const int rem = idx - g * 60;
        const int b   = rem >> 1;
        const int i   = rem & 1;
        const float c = coef[(ch0 + 2 * g + i) * NB + b];
        unsigned long long d;
        asm("mov.b64 %0, {%1, %1};" : "=l"(d) : "f"(c));
        scw2[idx] = d;
    }

    const float4* pp = (const float4*)(pos + 3 * p0);
    const float4 q0 = pp[0];
    const float4 q1 = pp[1];
    const float4 q2 = pp[2];

    float ba[NB], bb[NB], bc[NB], bd_[NB];
    basis_eval(q0.x, q0.y, q0.z, W.w, ba);
    basis_eval(q0.w, q1.x, q1.y, W.w, bb);
    basis_eval(q1.z, q1.w, q2.x, W.w, bc);
    basis_eval(q2.y, q2.z, q2.w, W.w, bd_);

    unsigned long long bd0[NB], bd1[NB];
#pragma unroll
    for (int b = 0; b < NB; ++b) {
        asm("mov.b64 %0, {%1, %2};" : "=l"(bd0[b]) : "f"(ba[b]), "f"(bb[b]));
        asm("mov.b64 %0, {%1, %2};" : "=l"(bd1[b]) : "f"(bc[b]), "f"(bd_[b]));
    }

    __syncthreads();

    // ---- unrolled x2: two 2-channel groups in flight, 8 acc chains ----
    const unsigned long long* cg = scw2;
    float* ob = out + (size_t)ch0 * NPTS + p0;
#pragma unroll 1
    for (int g = 0; g < NGH; g += 2) {
        unsigned long long a00 = 0ULL, a01 = 0ULL;   // group g,   ch+0
        unsigned long long a10 = 0ULL, a11 = 0ULL;   // group g,   ch+1
        unsigned long long a20 = 0ULL, a21 = 0ULL;   // group g+1, ch+0
        unsigned long long a30 = 0ULL, a31 = 0ULL;   // group g+1, ch+1
#pragma unroll
        for (int b = 0; b < NB; ++b) {
            const ulonglong2 cA = *(const ulonglong2*)(cg + b * 2);        // group g
            const ulonglong2 cB = *(const ulonglong2*)(cg + 60 + b * 2);   // group g+1
            asm("fma.rn.f32x2 %0, %1, %2, %0;" : "+l"(a00) : "l"(bd0[b]), "l"(cA.x));
            asm("fma.rn.f32x2 %0, %1, %2, %0;" : "+l"(a01) : "l"(bd1[b]), "l"(cA.x));
            asm("fma.rn.f32x2 %0, %1, %2, %0;" : "+l"(a10) : "l"(bd0[b]), "l"(cA.y));
            asm("fma.rn.f32x2 %0, %1, %2, %0;" : "+l"(a11) : "l"(bd1[b]), "l"(cA.y));
            asm("fma.rn.f32x2 %0, %1, %2, %0;" : "+l"(a20) : "l"(bd0[b]), "l"(cB.x));
            asm("fma.rn.f32x2 %0, %1, %2, %0;" : "+l"(a21) : "l"(bd1[b]), "l"(cB.x));
            asm("fma.rn.f32x2 %0, %1, %2, %0;" : "+l"(a30) : "l"(bd0[b]), "l"(cB.y));
            asm("fma.rn.f32x2 %0, %1, %2, %0;" : "+l"(a31) : "l"(bd1[b]), "l"(cB.y));
        }
        *(ulonglong2*)(ob)            = make_ulonglong2(a00, a01);
        *(ulonglong2*)(ob + NPTS)     = make_ulonglong2(a10, a11);
        *(ulonglong2*)(ob + 2 * NPTS) = make_ulonglong2(a20, a21);
        *(ulonglong2*)(ob + 3 * NPTS) = make_ulonglong2(a30, a31);
        cg += NB * 4;
        ob += 4 * NPTS;
    }
}

extern "C" void kernel_launch(void* const* d_in, const int* in_sizes, int n_in,
                              void* d_out, int out_size)
{
    const float* pos  = (const float*)d_in[0];
    const float* coef = (const float*)d_in[1];
    if (n_in >= 2 && in_sizes[0] == NOI * NB) {
        coef = (const float*)d_in[0];
        pos  = (const float*)d_in[1];
    }

    const double PI  = 3.14159265358979323846;
    const double K00 = sqrt(1.0 / (4.0 * PI));
    const double K10 = sqrt(3.0 / (4.0 * PI));
    const double K20 = sqrt(5.0 / (4.0 * PI));
    const double K30 = sqrt(7.0 / (4.0 * PI));
    const double A11 = sqrt(3.0 / (4.0 * PI));
    const double A21 = sqrt(5.0 / (12.0 * PI));
    const double A22 = sqrt(5.0 / (48.0 * PI));
    const double A31 = sqrt(7.0 / (24.0 * PI));
    const double A32 = sqrt(7.0 / (240.0 * PI));
    const double A33 = sqrt(7.0 / (1440.0 * PI));

    const double C10 = 2.0;
    const double C20 = sqrt(1.0 / 8.0);
    const double C21 = sqrt(1.0 / 24.0);
    const double C30 = sqrt(16.0 / 972.0);
    const double C31 = sqrt(8.0 / 3888.0);
    const double C32 = sqrt(8.0 / 19440.0);
    const double C40 = sqrt(6.0 / 1536.0);
    const double C41 = sqrt(2.0 / 7680.0);
    const double C42 = sqrt(1.0 / 46080.0);
    const double C43 = sqrt(1.0 / 322560.0);

    WParams W;
    const double w[NB] = {
        C10 * K00,
        C20 * K00,
        C21 * A11, C21 * K10, C21 * A11,
        C30 * K00,
        C31 * A11, C31 * K10, C31 * A11,
        C32 * A22, C32 * A21, C32 * K20, C32 * A21, C32 * A22,
        C40 * K00,
        C41 * A11, C41 * K10, C41 * A11,
        C42 * A22, C42 * A21, C42 * K20, C42 * A21, C42 * A22,
        C43 * A33, C43 * A32, C43 * A31, C43 * K30,
        C43 * A31, C43 * A32, C43 * A33
    };
    for (int i = 0; i < NB; ++i) W.w[i] = (float)w[i];

    dcconv_regbasis_u2<<<2 * (NPTS / (4 * THREADS)), THREADS>>>(pos, coef, (float*)d_out, W);
    (void)out_size;
}